// round 1
// baseline (speedup 1.0000x reference)
#include <cuda_runtime.h>
#include <math.h>

#define D_FEAT 128
#define HID 64
#define MAX_NODES 100000

// Scratch: per-node projected features y[n][0:64] = embed[n] @ W1[0:128],
//          y[n][64:128] = embed[n] @ W1[128:256]. 51.2 MB, L2-resident.
__device__ float g_y[(size_t)MAX_NODES * D_FEAT];
// g_c[0:64] = embed[src]@W1[256:384] + embed[dst]@W1[384:512] + b1 ; g_c[64] = b2
__device__ float g_c[HID + 1];

// ---------------------------------------------------------------------------
// Kernel 1: edge-invariant constant vector c (one block, 64 threads)
// ---------------------------------------------------------------------------
__global__ void const_kernel(const float* __restrict__ embed,
                             const float* __restrict__ W1,
                             const float* __restrict__ b1,
                             const float* __restrict__ b2,
                             const int* __restrict__ srcp,
                             const int* __restrict__ dstp) {
    int j = threadIdx.x;
    if (j >= HID) return;
    int s = srcp[0];
    int d = dstp[0];
    const float* es = embed + (size_t)s * D_FEAT;
    const float* ed = embed + (size_t)d * D_FEAT;
    float acc = b1[j];
#pragma unroll 8
    for (int k = 0; k < D_FEAT; ++k) {
        acc = fmaf(es[k], W1[(2 * D_FEAT + k) * HID + j], acc);
        acc = fmaf(ed[k], W1[(3 * D_FEAT + k) * HID + j], acc);
    }
    g_c[j] = acc;
    if (j == 0) g_c[HID] = b2[0];
}

// ---------------------------------------------------------------------------
// Kernel 2: node GEMM  y[M x 128] = embed[M x 128] @ Wc[128 x 128]
//   Wc[k][j] = (j < 64) ? W1[k][j] : W1[128+k][j-64]
// Tile: 64 rows x 128 cols per block. Full Wc in smem (64KB) + A tile
// (64 x 132 padded, 33.8KB). 256 threads, each computes 4x8 register tile.
// ---------------------------------------------------------------------------
#define AP 132  // padded A row stride (floats) to avoid smem bank conflicts

__global__ __launch_bounds__(256, 2)
void node_gemm(const float* __restrict__ embed,
               const float* __restrict__ W1,
               int M) {
    extern __shared__ float sm[];
    float* sW = sm;                 // [128][128]
    float* sA = sm + 128 * 128;     // [64][AP]

    int tid = threadIdx.x;

    // Load fused weight matrix
    for (int i = tid; i < 128 * 128; i += 256) {
        int k = i >> 7;
        int j = i & 127;
        sW[i] = (j < HID) ? W1[k * HID + j]
                          : W1[(D_FEAT + k) * HID + (j - HID)];
    }

    int row0 = blockIdx.x * 64;
    int rows = M - row0;
    if (rows > 64) rows = 64;

    // Load A tile (coalesced scalar loads into padded layout)
    for (int i = tid; i < rows * 128; i += 256) {
        sA[(i >> 7) * AP + (i & 127)] = embed[(size_t)row0 * 128 + i];
    }
    __syncthreads();

    int tx = tid & 15;   // col group: 8 cols
    int ty = tid >> 4;   // row group: 4 rows

    float acc[4][8];
#pragma unroll
    for (int i = 0; i < 4; ++i)
#pragma unroll
        for (int j = 0; j < 8; ++j) acc[i][j] = 0.f;

#pragma unroll 4
    for (int k = 0; k < 128; ++k) {
        float a[4];
#pragma unroll
        for (int i = 0; i < 4; ++i) a[i] = sA[(ty * 4 + i) * AP + k];
        float4 bv0 = *(const float4*)&sW[k * 128 + tx * 8];
        float4 bv1 = *(const float4*)&sW[k * 128 + tx * 8 + 4];
#pragma unroll
        for (int i = 0; i < 4; ++i) {
            acc[i][0] = fmaf(a[i], bv0.x, acc[i][0]);
            acc[i][1] = fmaf(a[i], bv0.y, acc[i][1]);
            acc[i][2] = fmaf(a[i], bv0.z, acc[i][2]);
            acc[i][3] = fmaf(a[i], bv0.w, acc[i][3]);
            acc[i][4] = fmaf(a[i], bv1.x, acc[i][4]);
            acc[i][5] = fmaf(a[i], bv1.y, acc[i][5]);
            acc[i][6] = fmaf(a[i], bv1.z, acc[i][6]);
            acc[i][7] = fmaf(a[i], bv1.w, acc[i][7]);
        }
    }

#pragma unroll
    for (int i = 0; i < 4; ++i) {
        int r = ty * 4 + i;
        if (r < rows) {
            float* yp = g_y + ((size_t)(row0 + r)) * 128 + tx * 8;
            *(float4*)yp     = make_float4(acc[i][0], acc[i][1], acc[i][2], acc[i][3]);
            *(float4*)(yp+4) = make_float4(acc[i][4], acc[i][5], acc[i][6], acc[i][7]);
        }
    }
}

// ---------------------------------------------------------------------------
// Kernel 3: edge kernel — one warp per edge.
//   h[j] = relu(y[col][j] + y[row][64+j] + c[j]);  w = h . W2
//   out = sigmoid(logit(noise) + w + b2)
// Lane i handles hidden elements 2i, 2i+1 (float2 gathers, 256B coalesced
// per warp from the L2-resident y table).
// ---------------------------------------------------------------------------
__global__ void edge_kernel(const float* __restrict__ W2,
                            const float* __restrict__ noise,
                            const int* __restrict__ col,
                            const int* __restrict__ row,
                            float* __restrict__ out,
                            int E) {
    int lane  = threadIdx.x & 31;
    int warp  = blockIdx.x * (blockDim.x >> 5) + (threadIdx.x >> 5);
    int nwarp = gridDim.x * (blockDim.x >> 5);

    float2 c2 = *(const float2*)&g_c[2 * lane];
    float2 w2 = make_float2(W2[2 * lane], W2[2 * lane + 1]);
    float  bias2 = g_c[HID];

    for (int e = warp; e < E; e += nwarp) {
        int ci = col[e];
        int ri = row[e];
        float2 a = *((const float2*)(g_y + (size_t)ci * 128) + lane);
        float2 b = *((const float2*)(g_y + (size_t)ri * 128 + 64) + lane);

        float ha = a.x + b.x + c2.x; ha = ha > 0.f ? ha : 0.f;
        float hb = a.y + b.y + c2.y; hb = hb > 0.f ? hb : 0.f;
        float s = fmaf(ha, w2.x, hb * w2.y);

#pragma unroll
        for (int o = 16; o; o >>= 1) s += __shfl_xor_sync(0xffffffffu, s, o);

        if (lane == 0) {
            float nz = noise[e];
            float g = logf(nz) - log1pf(-nz) + s + bias2;
            out[e] = 1.f / (1.f + expf(-g));
        }
    }
}

// ---------------------------------------------------------------------------
extern "C" void kernel_launch(void* const* d_in, const int* in_sizes, int n_in,
                              void* d_out, int out_size) {
    const float* embed = (const float*)d_in[0];
    const float* W1    = (const float*)d_in[1];
    const float* b1    = (const float*)d_in[2];
    const float* W2    = (const float*)d_in[3];
    const float* b2    = (const float*)d_in[4];
    const float* noise = (const float*)d_in[5];
    const int*   col   = (const int*)d_in[6];
    const int*   row   = (const int*)d_in[7];
    const int*   srcp  = (const int*)d_in[8];
    const int*   dstp  = (const int*)d_in[9];

    int M = in_sizes[0] / D_FEAT;   // nodes
    int E = in_sizes[6];            // edges

    size_t smem = (size_t)(128 * 128 + 64 * AP) * sizeof(float);  // 99,328 B
    cudaFuncSetAttribute(node_gemm, cudaFuncAttributeMaxDynamicSharedMemorySize,
                         (int)smem);

    const_kernel<<<1, 64>>>(embed, W1, b1, b2, srcp, dstp);
    node_gemm<<<(M + 63) / 64, 256, smem>>>(embed, W1, M);
    edge_kernel<<<2048, 256>>>(W2, noise, col, row, (float*)d_out, E);
}

// round 2
// speedup vs baseline: 1.3418x; 1.3418x over previous
#include <cuda_runtime.h>
#include <math.h>

#define D_FEAT 128
#define HID 64
#define MAX_NODES 100000

// Per-node projected features: y[n][0:64] = embed[n]@W1[0:128],
// y[n][64:128] = embed[n]@W1[128:256]. 51.2 MB, L2-resident.
__device__ float g_y[(size_t)MAX_NODES * 128];
// g_c[0:64] = embed[src]@W1[256:384] + embed[dst]@W1[384:512] + b1 ; g_c[64]=b2
__device__ float g_c[HID + 1];

typedef unsigned long long ull;

__device__ __forceinline__ ull fma2(ull a, ull b, ull c) {
    ull d;
    asm("fma.rn.f32x2 %0, %1, %2, %3;" : "=l"(d) : "l"(a), "l"(b), "l"(c));
    return d;
}
__device__ __forceinline__ ull splat2(float x) {
    ull d;
    asm("mov.b64 %0, {%1, %1};" : "=l"(d) : "f"(x));
    return d;
}

// ---------------------------------------------------------------------------
// Kernel 1: edge-invariant vector c. 512 threads: 8 k-groups x 64 outputs.
// W1 row for term t (t<256): row 256+t works for both src (t<128) and
// dst (t>=128) blocks: 256+t = 384+(t-128).
// ---------------------------------------------------------------------------
__global__ void const_kernel(const float* __restrict__ embed,
                             const float* __restrict__ W1,
                             const float* __restrict__ b1,
                             const float* __restrict__ b2,
                             const int* __restrict__ srcp,
                             const int* __restrict__ dstp) {
    __shared__ float part[8][HID];
    int j = threadIdx.x & 63;
    int g = threadIdx.x >> 6;   // 0..7
    int s = srcp[0];
    int d = dstp[0];
    const float* es = embed + (size_t)s * D_FEAT;
    const float* ed = embed + (size_t)d * D_FEAT;
    float acc = 0.f;
#pragma unroll 8
    for (int t = g * 32; t < g * 32 + 32; ++t) {
        float e = (t < 128) ? es[t] : ed[t - 128];
        acc = fmaf(e, W1[(256 + t) * HID + j], acc);
    }
    part[g][j] = acc;
    __syncthreads();
    if (threadIdx.x < 64) {
        float r = b1[j];
#pragma unroll
        for (int g2 = 0; g2 < 8; ++g2) r += part[g2][j];
        g_c[j] = r;
        if (j == 0) g_c[HID] = b2[0];
    }
}

// ---------------------------------------------------------------------------
// Kernel 2: node GEMM  y[M x 128] = embed[M x 128] @ Wc[128 x 128]
//   Wc[k][j] = (j<64) ? W1[k][j] : W1[128+k][j-64]
// 128x128 block tile, 256 threads, 8 rows x 8 cols per thread,
// packed-f32x2 accumulators (column pairs), fma.rn.f32x2 inner loop.
// ---------------------------------------------------------------------------
#define AP 132  // padded A row stride (floats)

__global__ __launch_bounds__(256, 1)
void node_gemm(const float* __restrict__ embed,
               const float* __restrict__ W1,
               int M) {
    extern __shared__ float sm[];
    float* sW = sm;                 // [128][128], row k major
    float* sA = sm + 128 * 128;     // [128][AP]

    int tid = threadIdx.x;

    // Build fused weight matrix in smem
    for (int i = tid; i < 128 * 128; i += 256) {
        int k = i >> 7;
        int j = i & 127;
        sW[i] = (j < HID) ? W1[k * HID + j]
                          : W1[(D_FEAT + k) * HID + (j - HID)];
    }

    int row0 = blockIdx.x * 128;
    int rows = M - row0;
    if (rows > 128) rows = 128;

    // Load A tile with float4 loads (zero-fill OOB rows)
    for (int i = tid; i < 128 * 32; i += 256) {
        int r = i >> 5;
        int c4 = (i & 31) * 4;
        float4 v = (r < rows)
            ? *(const float4*)&embed[(size_t)(row0 + r) * 128 + c4]
            : make_float4(0.f, 0.f, 0.f, 0.f);
        *(float4*)&sA[r * AP + c4] = v;
    }
    __syncthreads();

    int tx = tid & 15;   // col group of 8 (4 packed pairs)
    int ty = tid >> 4;   // row group of 8

    ull acc[8][4];
#pragma unroll
    for (int i = 0; i < 8; ++i)
#pragma unroll
        for (int j = 0; j < 4; ++j) acc[i][j] = 0ull;

    const float* aBase = sA + ty * 8 * AP;
    const float* bBase = sW + tx * 8;

#pragma unroll 4
    for (int k = 0; k < 128; ++k) {
        ull av[8];
#pragma unroll
        for (int i = 0; i < 8; ++i) av[i] = splat2(aBase[i * AP + k]);
        ulonglong2 B0 = *(const ulonglong2*)&bBase[k * 128];       // cols 0..3
        ulonglong2 B1 = *(const ulonglong2*)&bBase[k * 128 + 4];   // cols 4..7
#pragma unroll
        for (int i = 0; i < 8; ++i) {
            acc[i][0] = fma2(av[i], B0.x, acc[i][0]);
            acc[i][1] = fma2(av[i], B0.y, acc[i][1]);
            acc[i][2] = fma2(av[i], B1.x, acc[i][2]);
            acc[i][3] = fma2(av[i], B1.y, acc[i][3]);
        }
    }

#pragma unroll
    for (int i = 0; i < 8; ++i) {
        int r = ty * 8 + i;
        if (r < rows) {
            ull* yp = (ull*)(g_y + (size_t)(row0 + r) * 128 + tx * 8);
            *(ulonglong2*)yp       = make_ulonglong2(acc[i][0], acc[i][1]);
            *(ulonglong2*)(yp + 2) = make_ulonglong2(acc[i][2], acc[i][3]);
        }
    }
}

// ---------------------------------------------------------------------------
// Kernel 3: edge kernel — 2 edges per warp, 16 lanes per edge.
//   Each lane handles 4 hidden elems via float4 gathers (256B/edge/side).
//   h = relu(y[col][j] + y[row][64+j] + c[j]); s = h.W2; out = sigmoid(...)
// ---------------------------------------------------------------------------
__global__ void edge_kernel(const float* __restrict__ W2,
                            const float* __restrict__ noise,
                            const int* __restrict__ col,
                            const int* __restrict__ row,
                            float* __restrict__ out,
                            int E) {
    int lane = threadIdx.x & 31;
    int half = lane >> 4;       // which edge of the pair
    int l16  = lane & 15;
    int warp  = blockIdx.x * (blockDim.x >> 5) + (threadIdx.x >> 5);
    int nwarp = gridDim.x * (blockDim.x >> 5);

    float4 c4 = *(const float4*)&g_c[l16 * 4];
    float4 w4 = *(const float4*)&W2[l16 * 4];
    float bias = g_c[HID];

    for (int base = 2 * warp; base < E; base += 2 * nwarp) {
        int e = base + half;
        bool ok = e < E;
        int ei = ok ? e : 0;
        int ci = col[ei];
        int ri = row[ei];

        float4 a = *(const float4*)(g_y + (size_t)ci * 128 + l16 * 4);
        float4 b = *(const float4*)(g_y + (size_t)ri * 128 + 64 + l16 * 4);

        float h0 = fmaxf(a.x + b.x + c4.x, 0.f);
        float h1 = fmaxf(a.y + b.y + c4.y, 0.f);
        float h2 = fmaxf(a.z + b.z + c4.z, 0.f);
        float h3 = fmaxf(a.w + b.w + c4.w, 0.f);
        float s = fmaf(h0, w4.x, fmaf(h1, w4.y, fmaf(h2, w4.z, h3 * w4.w)));

        s += __shfl_xor_sync(0xffffffffu, s, 8);
        s += __shfl_xor_sync(0xffffffffu, s, 4);
        s += __shfl_xor_sync(0xffffffffu, s, 2);
        s += __shfl_xor_sync(0xffffffffu, s, 1);

        if (ok && l16 == 0) {
            float nz = noise[e];
            float g = logf(nz) - log1pf(-nz) + s + bias;
            out[e] = 1.f / (1.f + expf(-g));
        }
    }
}

// ---------------------------------------------------------------------------
extern "C" void kernel_launch(void* const* d_in, const int* in_sizes, int n_in,
                              void* d_out, int out_size) {
    const float* embed = (const float*)d_in[0];
    const float* W1    = (const float*)d_in[1];
    const float* b1    = (const float*)d_in[2];
    const float* W2    = (const float*)d_in[3];
    const float* b2    = (const float*)d_in[4];
    const float* noise = (const float*)d_in[5];
    const int*   col   = (const int*)d_in[6];
    const int*   row   = (const int*)d_in[7];
    const int*   srcp  = (const int*)d_in[8];
    const int*   dstp  = (const int*)d_in[9];

    int M = in_sizes[0] / D_FEAT;   // nodes
    int E = in_sizes[6];            // edges

    size_t smem = (size_t)(128 * 128 + 128 * AP) * sizeof(float);  // 133,120 B
    cudaFuncSetAttribute(node_gemm, cudaFuncAttributeMaxDynamicSharedMemorySize,
                         (int)smem);

    const_kernel<<<1, 512>>>(embed, W1, b1, b2, srcp, dstp);
    node_gemm<<<(M + 127) / 128, 256, smem>>>(embed, W1, M);
    edge_kernel<<<4096, 256>>>(W2, noise, col, row, (float*)d_out, E);
}

// round 5
// speedup vs baseline: 1.8108x; 1.3495x over previous
#include <cuda_runtime.h>
#include <cuda_fp16.h>
#include <math.h>

#define D_FEAT 128
#define HID 64
#define MAX_NODES 100000

// Per-node projected features in fp16: y[n][0:64] = embed[n]@W1[0:128],
// y[n][64:128] = embed[n]@W1[128:256]. 25.6 MB, L2-resident.
__device__ __half g_yh[(size_t)MAX_NODES * 128];
// g_c[0:64] = embed[src]@W1[256:384] + embed[dst]@W1[384:512] + b1 ; g_c[64]=b2
__device__ float g_c[HID + 1];

typedef unsigned long long ull;

__device__ __forceinline__ ull fma2(ull a, ull b, ull c) {
    ull d;
    asm("fma.rn.f32x2 %0, %1, %2, %3;" : "=l"(d) : "l"(a), "l"(b), "l"(c));
    return d;
}
__device__ __forceinline__ ull splat2(float x) {
    ull d;
    asm("mov.b64 %0, {%1, %1};" : "=l"(d) : "f"(x));
    return d;
}

// ---------------------------------------------------------------------------
// Kernel 1: node GEMM  y[M x 128] = embed[M x 128] @ Wc[128 x 128]  (fp16 out)
//   Wc[k][j] = (j<64) ? W1[k][j] : W1[128+k][j-64]
// 128x128 tile, 256 threads, 8x8 register tile, fma.rn.f32x2 inner loop.
// The LAST block instead computes the edge-invariant vector c (fused const).
// ---------------------------------------------------------------------------
#define AP 132  // padded A row stride (floats)

__global__ __launch_bounds__(256, 1)
void node_gemm(const float* __restrict__ embed,
               const float* __restrict__ W1,
               const float* __restrict__ b1,
               const float* __restrict__ b2,
               const int* __restrict__ srcp,
               const int* __restrict__ dstp,
               int M, int nblk) {
    extern __shared__ float sm[];
    int tid = threadIdx.x;

    if (blockIdx.x == (unsigned)nblk) {
        // ---- fused const block: c = emb[src]@W1[256:384] + emb[dst]@W1[384:512] + b1
        __shared__ float part[4][HID];
        int j = tid & 63;
        int g = tid >> 6;   // 0..3, each handles 64 t-values
        int s = srcp[0];
        int d = dstp[0];
        const float* es = embed + (size_t)s * D_FEAT;
        const float* ed = embed + (size_t)d * D_FEAT;
        float acc = 0.f;
#pragma unroll 8
        for (int t = g * 64; t < g * 64 + 64; ++t) {
            float e = (t < 128) ? es[t] : ed[t - 128];
            acc = fmaf(e, W1[(256 + t) * HID + j], acc);  // 256+t == 384+(t-128)
        }
        part[g][j] = acc;
        __syncthreads();
        if (tid < 64) {
            float r = b1[j] + part[0][j] + part[1][j] + part[2][j] + part[3][j];
            g_c[j] = r;
            if (j == 0) g_c[HID] = b2[0];
        }
        return;
    }

    float* sW = sm;                 // [128][128], row-k major
    float* sA = sm + 128 * 128;     // [128][AP]

    // Build fused weight matrix in smem
    for (int i = tid; i < 128 * 128; i += 256) {
        int k = i >> 7;
        int j = i & 127;
        sW[i] = (j < HID) ? W1[k * HID + j]
                          : W1[(D_FEAT + k) * HID + (j - HID)];
    }

    int row0 = blockIdx.x * 128;
    int rows = M - row0;
    if (rows > 128) rows = 128;

    for (int i = tid; i < 128 * 32; i += 256) {
        int r = i >> 5;
        int c4 = (i & 31) * 4;
        float4 v = (r < rows)
            ? *(const float4*)&embed[(size_t)(row0 + r) * 128 + c4]
            : make_float4(0.f, 0.f, 0.f, 0.f);
        *(float4*)&sA[r * AP + c4] = v;
    }
    __syncthreads();

    int tx = tid & 15;   // col group of 8 (4 packed pairs)
    int ty = tid >> 4;   // row group of 8

    ull acc[8][4];
#pragma unroll
    for (int i = 0; i < 8; ++i)
#pragma unroll
        for (int j = 0; j < 4; ++j) acc[i][j] = 0ull;

    const float* aBase = sA + ty * 8 * AP;
    const float* bBase = sW + tx * 8;

#pragma unroll 4
    for (int k = 0; k < 128; ++k) {
        ull av[8];
#pragma unroll
        for (int i = 0; i < 8; ++i) av[i] = splat2(aBase[i * AP + k]);
        ulonglong2 B0 = *(const ulonglong2*)&bBase[k * 128];
        ulonglong2 B1 = *(const ulonglong2*)&bBase[k * 128 + 4];
#pragma unroll
        for (int i = 0; i < 8; ++i) {
            acc[i][0] = fma2(av[i], B0.x, acc[i][0]);
            acc[i][1] = fma2(av[i], B0.y, acc[i][1]);
            acc[i][2] = fma2(av[i], B1.x, acc[i][2]);
            acc[i][3] = fma2(av[i], B1.y, acc[i][3]);
        }
    }

    // Epilogue: convert to fp16, 8 halves = one 16B store per row
#pragma unroll
    for (int i = 0; i < 8; ++i) {
        int r = ty * 8 + i;
        if (r < rows) {
            __half2 h[4];
#pragma unroll
            for (int j = 0; j < 4; ++j) {
                float2 f = *(float2*)&acc[i][j];
                h[j] = __floats2half2_rn(f.x, f.y);
            }
            *(uint4*)(g_yh + (size_t)(row0 + r) * 128 + tx * 8) = *(uint4*)h;
        }
    }
}

// ---------------------------------------------------------------------------
// Kernel 2: edge kernel — 4 edges per warp, 8 lanes per edge.
//   Lane loads 8 halves (16B) from each side: y[col][0:64], y[row][64:128].
//   h = relu(a + b + c); s = h.W2; out = sigmoid(logit(noise) + s + b2)
// ---------------------------------------------------------------------------
__global__ void edge_kernel(const float* __restrict__ W2,
                            const float* __restrict__ noise,
                            const int* __restrict__ col,
                            const int* __restrict__ row,
                            float* __restrict__ out,
                            int E) {
    int lane = threadIdx.x & 31;
    int sub  = lane >> 3;       // which edge of the quad (0..3)
    int l8   = lane & 7;
    int warp  = blockIdx.x * (blockDim.x >> 5) + (threadIdx.x >> 5);
    int nwarp = gridDim.x * (blockDim.x >> 5);

    float4 c0 = *(const float4*)&g_c[l8 * 8];
    float4 c1 = *(const float4*)&g_c[l8 * 8 + 4];
    float4 w0 = *(const float4*)&W2[l8 * 8];
    float4 w1 = *(const float4*)&W2[l8 * 8 + 4];
    float bias = g_c[HID];

    for (int base = 4 * warp; base < E; base += 4 * nwarp) {
        int e = base + sub;
        bool ok = e < E;
        int ei = ok ? e : 0;
        int ci = col[ei];
        int ri = row[ei];

        uint4 av = *(const uint4*)(g_yh + (size_t)ci * 128 + l8 * 8);
        uint4 bv = *(const uint4*)(g_yh + (size_t)ri * 128 + 64 + l8 * 8);

        const __half2* ah = (const __half2*)&av;
        const __half2* bh = (const __half2*)&bv;
        float2 a0 = __half22float2(ah[0]), a1 = __half22float2(ah[1]);
        float2 a2 = __half22float2(ah[2]), a3 = __half22float2(ah[3]);
        float2 b0 = __half22float2(bh[0]), b1 = __half22float2(bh[1]);
        float2 b2v = __half22float2(bh[2]), b3 = __half22float2(bh[3]);

        float h0 = fmaxf(a0.x + b0.x + c0.x, 0.f);
        float h1 = fmaxf(a0.y + b0.y + c0.y, 0.f);
        float h2 = fmaxf(a1.x + b1.x + c0.z, 0.f);
        float h3 = fmaxf(a1.y + b1.y + c0.w, 0.f);
        float h4 = fmaxf(a2.x + b2v.x + c1.x, 0.f);
        float h5 = fmaxf(a2.y + b2v.y + c1.y, 0.f);
        float h6 = fmaxf(a3.x + b3.x + c1.z, 0.f);
        float h7 = fmaxf(a3.y + b3.y + c1.w, 0.f);

        float s = fmaf(h0, w0.x, fmaf(h1, w0.y, fmaf(h2, w0.z, h3 * w0.w)));
        s = fmaf(h4, w1.x, fmaf(h5, w1.y, fmaf(h6, w1.z, fmaf(h7, w1.w, s))));

        s += __shfl_xor_sync(0xffffffffu, s, 4);
        s += __shfl_xor_sync(0xffffffffu, s, 2);
        s += __shfl_xor_sync(0xffffffffu, s, 1);

        if (ok && l8 == 0) {
            float nz = noise[e];
            float g = logf(nz) - log1pf(-nz) + s + bias;
            out[e] = 1.f / (1.f + expf(-g));
        }
    }
}

// ---------------------------------------------------------------------------
extern "C" void kernel_launch(void* const* d_in, const int* in_sizes, int n_in,
                              void* d_out, int out_size) {
    const float* embed = (const float*)d_in[0];
    const float* W1    = (const float*)d_in[1];
    const float* b1    = (const float*)d_in[2];
    const float* W2    = (const float*)d_in[3];
    const float* b2    = (const float*)d_in[4];
    const float* noise = (const float*)d_in[5];
    const int*   col   = (const int*)d_in[6];
    const int*   row   = (const int*)d_in[7];
    const int*   srcp  = (const int*)d_in[8];
    const int*   dstp  = (const int*)d_in[9];

    int M = in_sizes[0] / D_FEAT;   // nodes
    int E = in_sizes[6];            // edges

    size_t smem = (size_t)(128 * 128 + 128 * AP) * sizeof(float);  // 133,120 B
    cudaFuncSetAttribute(node_gemm, cudaFuncAttributeMaxDynamicSharedMemorySize,
                         (int)smem);

    int nblk = (M + 127) / 128;
    node_gemm<<<nblk + 1, 256, smem>>>(embed, W1, b1, b2, srcp, dstp, M, nblk);
    edge_kernel<<<4096, 256>>>(W2, noise, col, row, (float*)d_out, E);
}

// round 7
// speedup vs baseline: 3.9809x; 2.1984x over previous
#include <cuda_runtime.h>
#include <cuda_fp16.h>
#include <math.h>
#include <stdint.h>

#define D_FEAT 128
#define HID 64

// Per-node projected features in fp16 (25.6 MB, L2-resident).
__device__ __half g_yh[(size_t)100000 * 128];
// g_c[0:64] = emb[src]@W1[256:384] + emb[dst]@W1[384:512] + b1 ; g_c[64]=b2
__device__ float g_c[HID + 1];
// WcT in fp16, row-major [j][k]: g_Bt[j*128+k] = Wc[k][j]
__device__ __half g_Bt[128 * 128];

// ---------------------------------------------------------------------------
// Kernel 1 (prep): block 0 builds g_Bt (fp16 WcT), block 1 builds c-vector.
// ---------------------------------------------------------------------------
__global__ void prep_kernel(const float* __restrict__ embed,
                            const float* __restrict__ W1,
                            const float* __restrict__ b1,
                            const float* __restrict__ b2,
                            const int* __restrict__ srcp,
                            const int* __restrict__ dstp) {
    int tid = threadIdx.x;
    if (blockIdx.x == 0) {
        for (int idx = tid; idx < 128 * 128; idx += 256) {
            int j = idx >> 7;   // output col = WcT row
            int k = idx & 127;  // K index
            float v = (j < HID) ? W1[k * HID + j]
                                : W1[(D_FEAT + k) * HID + (j - HID)];
            g_Bt[idx] = __float2half_rn(v);
        }
    } else {
        __shared__ float part[4][HID];
        int j = tid & 63;
        int g = tid >> 6;   // 0..3
        int s = srcp[0];
        int d = dstp[0];
        const float* es = embed + (size_t)s * D_FEAT;
        const float* ed = embed + (size_t)d * D_FEAT;
        float acc = 0.f;
#pragma unroll 8
        for (int t = g * 64; t < g * 64 + 64; ++t) {
            float e = (t < 128) ? es[t] : ed[t - 128];
            acc = fmaf(e, W1[(256 + t) * HID + j], acc);  // 256+t == 384+(t-128)
        }
        part[g][j] = acc;
        __syncthreads();
        if (tid < 64) {
            g_c[j] = b1[j] + part[0][j] + part[1][j] + part[2][j] + part[3][j];
            if (j == 0) g_c[HID] = b2[0];
        }
    }
}

// ---------------------------------------------------------------------------
// Kernel 2: node GEMM via mma.sync.m16n8k16 (fp16 in, fp32 accum).
// y[M x 128] = embed[M x 128] @ Wc[128 x 128], fp16 output to g_yh.
// CTA: 128x128 tile, 256 threads = 8 warps (4 M-blocks x 2 N-blocks),
// warp tile 32x64 = 2x8 fragments, K-loop of 8 steps of 16.
// smem rows padded to 136 halves (272 B) for conflict-free frag loads.
// ---------------------------------------------------------------------------
#define SROW 272            // bytes per padded smem row (136 halves)
#define SM_A 0              // A tile: 128 * 272 = 34816 B
#define SM_B 34816          // B tile: 128 * 272 = 34816 B
#define SM_TOTAL 69632

__device__ __forceinline__ void mma16816(float* c, const uint32_t* a,
                                         const uint32_t* b) {
    asm volatile(
        "mma.sync.aligned.m16n8k16.row.col.f32.f16.f16.f32 "
        "{%0,%1,%2,%3}, {%4,%5,%6,%7}, {%8,%9}, {%0,%1,%2,%3};"
        : "+f"(c[0]), "+f"(c[1]), "+f"(c[2]), "+f"(c[3])
        : "r"(a[0]), "r"(a[1]), "r"(a[2]), "r"(a[3]), "r"(b[0]), "r"(b[1]));
}

__global__ __launch_bounds__(256, 1)
void node_gemm_mma(const float* __restrict__ embed, int M) {
    extern __shared__ char smem[];
    int tid = threadIdx.x;

    int row0 = blockIdx.x * 128;
    int rows = M - row0;
    if (rows > 128) rows = 128;

    // Copy WcT (fp16, 32 KB) into padded smem B
    for (int i = tid; i < 2048; i += 256) {
        int r = i >> 4;
        int q = i & 15;
        *(uint4*)(smem + SM_B + r * SROW + q * 16) = ((const uint4*)g_Bt)[i];
    }

    // Load + convert A tile: chunk = 8 floats -> 8 halves (16 B)
    for (int idx = tid; idx < 2048; idx += 256) {
        int r  = idx >> 4;
        int cc = idx & 15;
        float4 f0, f1;
        if (r < rows) {
            const float* src = embed + (size_t)(row0 + r) * 128 + cc * 8;
            f0 = *(const float4*)src;
            f1 = *(const float4*)(src + 4);
        } else {
            f0 = f1 = make_float4(0.f, 0.f, 0.f, 0.f);
        }
        __half2 h[4];
        h[0] = __floats2half2_rn(f0.x, f0.y);
        h[1] = __floats2half2_rn(f0.z, f0.w);
        h[2] = __floats2half2_rn(f1.x, f1.y);
        h[3] = __floats2half2_rn(f1.z, f1.w);
        *(uint4*)(smem + SM_A + r * SROW + cc * 16) = *(uint4*)h;
    }
    __syncthreads();

    int w    = tid >> 5;
    int lane = tid & 31;
    int g    = lane >> 2;       // group 0..7
    int tg   = lane & 3;        // thread-in-group 0..3
    int mw   = (w & 3) * 32;    // warp M origin within tile
    int nw   = (w >> 2) * 64;   // warp N origin within tile

    float acc[2][8][4];
#pragma unroll
    for (int mi = 0; mi < 2; ++mi)
#pragma unroll
        for (int nj = 0; nj < 8; ++nj)
#pragma unroll
            for (int q = 0; q < 4; ++q) acc[mi][nj][q] = 0.f;

    const char* pa0 = smem + SM_A + (mw + g) * SROW + tg * 4;
    const char* pb0 = smem + SM_B + (nw + g) * SROW + tg * 4;

#pragma unroll
    for (int ks = 0; ks < 8; ++ks) {
        int kb = ks * 32;   // byte offset of k-block (16 halves)
        uint32_t a[2][4];
#pragma unroll
        for (int mi = 0; mi < 2; ++mi) {
            const char* p = pa0 + mi * 16 * SROW + kb;
            a[mi][0] = *(const uint32_t*)p;
            a[mi][1] = *(const uint32_t*)(p + 8 * SROW);
            a[mi][2] = *(const uint32_t*)(p + 16);
            a[mi][3] = *(const uint32_t*)(p + 8 * SROW + 16);
        }
        uint32_t b[8][2];
#pragma unroll
        for (int nj = 0; nj < 8; ++nj) {
            const char* p = pb0 + nj * 8 * SROW + kb;
            b[nj][0] = *(const uint32_t*)p;
            b[nj][1] = *(const uint32_t*)(p + 16);
        }
#pragma unroll
        for (int mi = 0; mi < 2; ++mi)
#pragma unroll
            for (int nj = 0; nj < 8; ++nj)
                mma16816(acc[mi][nj], a[mi], b[nj]);
    }

    // Epilogue: write fp16 half2 per fragment row
#pragma unroll
    for (int mi = 0; mi < 2; ++mi) {
        int r0 = row0 + mw + mi * 16 + g;
        int r1 = r0 + 8;
#pragma unroll
        for (int nj = 0; nj < 8; ++nj) {
            int jc = nw + nj * 8 + tg * 2;
            if (r0 < M)
                *(__half2*)(g_yh + (size_t)r0 * 128 + jc) =
                    __floats2half2_rn(acc[mi][nj][0], acc[mi][nj][1]);
            if (r1 < M)
                *(__half2*)(g_yh + (size_t)r1 * 128 + jc) =
                    __floats2half2_rn(acc[mi][nj][2], acc[mi][nj][3]);
        }
    }
}

// ---------------------------------------------------------------------------
// Kernel 3: edge kernel — 4 edges per warp, 8 lanes per edge.
// ---------------------------------------------------------------------------
__global__ void edge_kernel(const float* __restrict__ W2,
                            const float* __restrict__ noise,
                            const int* __restrict__ col,
                            const int* __restrict__ row,
                            float* __restrict__ out,
                            int E) {
    int lane = threadIdx.x & 31;
    int sub  = lane >> 3;
    int l8   = lane & 7;
    int warp  = blockIdx.x * (blockDim.x >> 5) + (threadIdx.x >> 5);
    int nwarp = gridDim.x * (blockDim.x >> 5);

    float4 c0 = *(const float4*)&g_c[l8 * 8];
    float4 c1 = *(const float4*)&g_c[l8 * 8 + 4];
    float4 w0 = *(const float4*)&W2[l8 * 8];
    float4 w1 = *(const float4*)&W2[l8 * 8 + 4];
    float bias = g_c[HID];

    for (int base = 4 * warp; base < E; base += 4 * nwarp) {
        int e = base + sub;
        bool ok = e < E;
        int ei = ok ? e : 0;
        int ci = col[ei];
        int ri = row[ei];

        uint4 av = *(const uint4*)(g_yh + (size_t)ci * 128 + l8 * 8);
        uint4 bv = *(const uint4*)(g_yh + (size_t)ri * 128 + 64 + l8 * 8);

        const __half2* ah = (const __half2*)&av;
        const __half2* bh = (const __half2*)&bv;
        float2 a0 = __half22float2(ah[0]), a1 = __half22float2(ah[1]);
        float2 a2 = __half22float2(ah[2]), a3 = __half22float2(ah[3]);
        float2 b0 = __half22float2(bh[0]), b1 = __half22float2(bh[1]);
        float2 b2v = __half22float2(bh[2]), b3 = __half22float2(bh[3]);

        float h0 = fmaxf(a0.x + b0.x + c0.x, 0.f);
        float h1 = fmaxf(a0.y + b0.y + c0.y, 0.f);
        float h2 = fmaxf(a1.x + b1.x + c0.z, 0.f);
        float h3 = fmaxf(a1.y + b1.y + c0.w, 0.f);
        float h4 = fmaxf(a2.x + b2v.x + c1.x, 0.f);
        float h5 = fmaxf(a2.y + b2v.y + c1.y, 0.f);
        float h6 = fmaxf(a3.x + b3.x + c1.z, 0.f);
        float h7 = fmaxf(a3.y + b3.y + c1.w, 0.f);

        float s = fmaf(h0, w0.x, fmaf(h1, w0.y, fmaf(h2, w0.z, h3 * w0.w)));
        s = fmaf(h4, w1.x, fmaf(h5, w1.y, fmaf(h6, w1.z, fmaf(h7, w1.w, s))));

        s += __shfl_xor_sync(0xffffffffu, s, 4);
        s += __shfl_xor_sync(0xffffffffu, s, 2);
        s += __shfl_xor_sync(0xffffffffu, s, 1);

        if (ok && l8 == 0) {
            float nz = noise[e];
            float g = logf(nz) - log1pf(-nz) + s + bias;
            out[e] = 1.f / (1.f + expf(-g));
        }
    }
}

// ---------------------------------------------------------------------------
extern "C" void kernel_launch(void* const* d_in, const int* in_sizes, int n_in,
                              void* d_out, int out_size) {
    const float* embed = (const float*)d_in[0];
    const float* W1    = (const float*)d_in[1];
    const float* b1    = (const float*)d_in[2];
    const float* W2    = (const float*)d_in[3];
    const float* b2    = (const float*)d_in[4];
    const float* noise = (const float*)d_in[5];
    const int*   col   = (const int*)d_in[6];
    const int*   row   = (const int*)d_in[7];
    const int*   srcp  = (const int*)d_in[8];
    const int*   dstp  = (const int*)d_in[9];

    int M = in_sizes[0] / D_FEAT;
    int E = in_sizes[6];

    cudaFuncSetAttribute(node_gemm_mma,
                         cudaFuncAttributeMaxDynamicSharedMemorySize, SM_TOTAL);

    int nblk = (M + 127) / 128;
    prep_kernel<<<2, 256>>>(embed, W1, b1, b2, srcp, dstp);
    node_gemm_mma<<<nblk, 256, SM_TOTAL>>>(embed, M);
    edge_kernel<<<4096, 256>>>(W2, noise, col, row, (float*)d_out, E);
}

// round 8
// speedup vs baseline: 4.6836x; 1.1765x over previous
#include <cuda_runtime.h>
#include <cuda_fp16.h>
#include <math.h>
#include <stdint.h>

#define D_FEAT 128
#define HID 64

// Per-node projected features in fp16 (25.6 MB, L2-resident).
__device__ __half g_yh[(size_t)100000 * 128];
// c vector (float) + bias
__device__ float g_c[HID + 1];
// half2-packed c and W2 for the edge kernel
__device__ __half2 g_ch2[HID / 2];
__device__ __half2 g_w2h2[HID / 2];

// ---------------------------------------------------------------------------
// Kernel 1: node GEMM via mma.sync.m16n8k16 (fp16 in, fp32 accum).
// y[M x 128] = embed[M x 128] @ Wc[128 x 128], fp16 output to g_yh.
// CTA: 128x128 tile, 256 threads = 8 warps (4 M x 2 N), warp 32x64.
// Each CTA self-builds the WcT smem tile from W1 (coalesced read, smem
// transpose). Block nblk computes the edge-invariant c vector instead.
// ---------------------------------------------------------------------------
#define SROW 272            // bytes per padded smem row (136 halves)
#define SM_A 0              // A tile: 128 * 272 = 34816 B
#define SM_B 34816          // B tile: 128 * 272 = 34816 B
#define SM_TOTAL 69632

__device__ __forceinline__ void mma16816(float* c, const uint32_t* a,
                                         const uint32_t* b) {
    asm volatile(
        "mma.sync.aligned.m16n8k16.row.col.f32.f16.f16.f32 "
        "{%0,%1,%2,%3}, {%4,%5,%6,%7}, {%8,%9}, {%0,%1,%2,%3};"
        : "+f"(c[0]), "+f"(c[1]), "+f"(c[2]), "+f"(c[3])
        : "r"(a[0]), "r"(a[1]), "r"(a[2]), "r"(a[3]), "r"(b[0]), "r"(b[1]));
}

__global__ __launch_bounds__(256, 1)
void node_gemm_mma(const float* __restrict__ embed,
                   const float* __restrict__ W1,
                   const float* __restrict__ b1,
                   const float* __restrict__ W2,
                   const float* __restrict__ b2,
                   const int* __restrict__ srcp,
                   const int* __restrict__ dstp,
                   int M, int nblk) {
    extern __shared__ char smem[];
    int tid = threadIdx.x;

    if (blockIdx.x == (unsigned)nblk) {
        // ---- c vector block: c = emb[src]@W1[256:384] + emb[dst]@W1[384:512] + b1
        __shared__ float part[4][HID];
        int j = tid & 63;
        int g = tid >> 6;   // 0..3
        int s = srcp[0];
        int d = dstp[0];
        const float* es = embed + (size_t)s * D_FEAT;
        const float* ed = embed + (size_t)d * D_FEAT;
        float acc = 0.f;
#pragma unroll 16
        for (int t = g * 64; t < g * 64 + 64; ++t) {
            float e = (t < 128) ? es[t] : ed[t - 128];
            acc = fmaf(e, W1[(256 + t) * HID + j], acc);  // 256+t == 384+(t-128)
        }
        part[g][j] = acc;
        __syncthreads();
        if (tid < 64) {
            float cj = b1[j] + part[0][j] + part[1][j] + part[2][j] + part[3][j];
            g_c[j] = cj;
            part[0][j] = cj;   // stash for pair packing
            if (j == 0) g_c[HID] = b2[0];
        }
        __syncthreads();
        if (tid < 32) {
            g_ch2[tid]  = __floats2half2_rn(part[0][2 * tid], part[0][2 * tid + 1]);
            g_w2h2[tid] = __floats2half2_rn(W2[2 * tid], W2[2 * tid + 1]);
        }
        return;
    }

    int row0 = blockIdx.x * 128;
    int rows = M - row0;
    if (rows > 128) rows = 128;

    // Build WcT smem tile from W1: read W1 rows 0..255 coalesced, write
    // transposed halves. idx = r*64 + c; (r<128 -> k=r, j=c) (r>=128 ->
    // k=r-128, j=c+64). B[j][k] at SM_B + j*SROW + 2k.
    for (int idx = tid; idx < 16384; idx += 256) {
        int r = idx >> 6;
        int c = idx & 63;
        int k = (r < 128) ? r : r - 128;
        int j = (r < 128) ? c : c + 64;
        *(__half*)(smem + SM_B + j * SROW + 2 * k) = __float2half_rn(W1[idx]);
    }

    // Load + convert A tile: chunk = 8 floats -> 8 halves (16 B)
    for (int idx = tid; idx < 2048; idx += 256) {
        int r  = idx >> 4;
        int cc = idx & 15;
        float4 f0, f1;
        if (r < rows) {
            const float* src = embed + (size_t)(row0 + r) * 128 + cc * 8;
            f0 = *(const float4*)src;
            f1 = *(const float4*)(src + 4);
        } else {
            f0 = f1 = make_float4(0.f, 0.f, 0.f, 0.f);
        }
        __half2 h[4];
        h[0] = __floats2half2_rn(f0.x, f0.y);
        h[1] = __floats2half2_rn(f0.z, f0.w);
        h[2] = __floats2half2_rn(f1.x, f1.y);
        h[3] = __floats2half2_rn(f1.z, f1.w);
        *(uint4*)(smem + SM_A + r * SROW + cc * 16) = *(uint4*)h;
    }
    __syncthreads();

    int w    = tid >> 5;
    int lane = tid & 31;
    int g    = lane >> 2;       // group 0..7
    int tg   = lane & 3;        // thread-in-group 0..3
    int mw   = (w & 3) * 32;    // warp M origin
    int nw   = (w >> 2) * 64;   // warp N origin

    float acc[2][8][4];
#pragma unroll
    for (int mi = 0; mi < 2; ++mi)
#pragma unroll
        for (int nj = 0; nj < 8; ++nj)
#pragma unroll
            for (int q = 0; q < 4; ++q) acc[mi][nj][q] = 0.f;

    const char* pa0 = smem + SM_A + (mw + g) * SROW + tg * 4;
    const char* pb0 = smem + SM_B + (nw + g) * SROW + tg * 4;

#pragma unroll
    for (int ks = 0; ks < 8; ++ks) {
        int kb = ks * 32;
        uint32_t a[2][4];
#pragma unroll
        for (int mi = 0; mi < 2; ++mi) {
            const char* p = pa0 + mi * 16 * SROW + kb;
            a[mi][0] = *(const uint32_t*)p;
            a[mi][1] = *(const uint32_t*)(p + 8 * SROW);
            a[mi][2] = *(const uint32_t*)(p + 16);
            a[mi][3] = *(const uint32_t*)(p + 8 * SROW + 16);
        }
        uint32_t b[8][2];
#pragma unroll
        for (int nj = 0; nj < 8; ++nj) {
            const char* p = pb0 + nj * 8 * SROW + kb;
            b[nj][0] = *(const uint32_t*)p;
            b[nj][1] = *(const uint32_t*)(p + 16);
        }
#pragma unroll
        for (int mi = 0; mi < 2; ++mi)
#pragma unroll
            for (int nj = 0; nj < 8; ++nj)
                mma16816(acc[mi][nj], a[mi], b[nj]);
    }

    // Epilogue: fp16 half2 stores
#pragma unroll
    for (int mi = 0; mi < 2; ++mi) {
        int r0 = row0 + mw + mi * 16 + g;
        int r1 = r0 + 8;
#pragma unroll
        for (int nj = 0; nj < 8; ++nj) {
            int jc = nw + nj * 8 + tg * 2;
            if (r0 < M)
                *(__half2*)(g_yh + (size_t)r0 * 128 + jc) =
                    __floats2half2_rn(acc[mi][nj][0], acc[mi][nj][1]);
            if (r1 < M)
                *(__half2*)(g_yh + (size_t)r1 * 128 + jc) =
                    __floats2half2_rn(acc[mi][nj][2], acc[mi][nj][3]);
        }
    }
}

// ---------------------------------------------------------------------------
// Kernel 2: edge kernel — 4 edges per warp, 8 lanes per edge, half2 math.
//   t = hmax2(a + b + c, 0); two 2-deep HFMA2 dot chains; fp32 finish.
// ---------------------------------------------------------------------------
__global__ void edge_kernel(const float* __restrict__ noise,
                            const int* __restrict__ col,
                            const int* __restrict__ row,
                            float* __restrict__ out,
                            int E) {
    int lane = threadIdx.x & 31;
    int sub  = lane >> 3;
    int l8   = lane & 7;
    int warp  = blockIdx.x * (blockDim.x >> 5) + (threadIdx.x >> 5);
    int nwarp = gridDim.x * (blockDim.x >> 5);

    uint4 cu = *(const uint4*)&g_ch2[l8 * 4];
    uint4 wu = *(const uint4*)&g_w2h2[l8 * 4];
    const __half2* c2 = (const __half2*)&cu;
    const __half2* w2 = (const __half2*)&wu;
    float bias = g_c[HID];
    __half2 z2 = __float2half2_rn(0.f);

    for (int base = 4 * warp; base < E; base += 4 * nwarp) {
        int e = base + sub;
        bool ok = e < E;
        int ei = ok ? e : 0;
        int ci = col[ei];
        int ri = row[ei];

        uint4 av = __ldg((const uint4*)(g_yh + (size_t)ci * 128 + l8 * 8));
        uint4 bv = __ldg((const uint4*)(g_yh + (size_t)ri * 128 + 64 + l8 * 8));

        const __half2* ah = (const __half2*)&av;
        const __half2* bh = (const __half2*)&bv;

        __half2 t0 = __hmax2(__hadd2(__hadd2(ah[0], bh[0]), c2[0]), z2);
        __half2 t1 = __hmax2(__hadd2(__hadd2(ah[1], bh[1]), c2[1]), z2);
        __half2 t2 = __hmax2(__hadd2(__hadd2(ah[2], bh[2]), c2[2]), z2);
        __half2 t3 = __hmax2(__hadd2(__hadd2(ah[3], bh[3]), c2[3]), z2);

        __half2 accA = __hfma2(t1, w2[1], __hmul2(t0, w2[0]));
        __half2 accB = __hfma2(t3, w2[3], __hmul2(t2, w2[2]));

        float2 fA = __half22float2(accA);
        float2 fB = __half22float2(accB);
        float s = (fA.x + fA.y) + (fB.x + fB.y);

        s += __shfl_xor_sync(0xffffffffu, s, 4);
        s += __shfl_xor_sync(0xffffffffu, s, 2);
        s += __shfl_xor_sync(0xffffffffu, s, 1);

        if (ok && l8 == 0) {
            float nz = noise[e];
            float g = logf(nz) - log1pf(-nz) + s + bias;
            out[e] = 1.f / (1.f + expf(-g));
        }
    }
}

// ---------------------------------------------------------------------------
extern "C" void kernel_launch(void* const* d_in, const int* in_sizes, int n_in,
                              void* d_out, int out_size) {
    const float* embed = (const float*)d_in[0];
    const float* W1    = (const float*)d_in[1];
    const float* b1    = (const float*)d_in[2];
    const float* W2    = (const float*)d_in[3];
    const float* b2    = (const float*)d_in[4];
    const float* noise = (const float*)d_in[5];
    const int*   col   = (const int*)d_in[6];
    const int*   row   = (const int*)d_in[7];
    const int*   srcp  = (const int*)d_in[8];
    const int*   dstp  = (const int*)d_in[9];

    int M = in_sizes[0] / D_FEAT;
    int E = in_sizes[6];

    cudaFuncSetAttribute(node_gemm_mma,
                         cudaFuncAttributeMaxDynamicSharedMemorySize, SM_TOTAL);

    int nblk = (M + 127) / 128;
    node_gemm_mma<<<nblk + 1, 256, SM_TOTAL>>>(embed, W1, b1, W2, b2,
                                               srcp, dstp, M, nblk);
    edge_kernel<<<4096, 256>>>(noise, col, row, (float*)d_out, E);
}

// round 9
// speedup vs baseline: 4.8712x; 1.0400x over previous
#include <cuda_runtime.h>
#include <cuda_fp16.h>
#include <math.h>
#include <stdint.h>

#define D_FEAT 128
#define HID 64

// Per-node projected features in fp16 (25.6 MB, L2-resident).
__device__ __half g_yh[(size_t)100000 * 128];
// c vector (float) + bias
__device__ float g_c[HID + 1];
// half2-packed c and W2 for the edge kernel
__device__ __half2 g_ch2[HID / 2];
__device__ __half2 g_w2h2[HID / 2];

// ---------------------------------------------------------------------------
// Kernel 1: node GEMM via mma.sync.m16n8k16 (fp16 in, fp32 accum).
// y[M x 128] = embed[M x 128] @ Wc[128 x 128], fp16 output to g_yh.
// CTA: 128x128 tile, 256 threads = 8 warps (4 M x 2 N), warp 32x64.
// 2 CTAs/SM so tile-fill of one overlaps MMA of the other.
// Block nblk computes the edge-invariant c vector instead.
// ---------------------------------------------------------------------------
#define SROW 272            // bytes per padded smem row (136 halves)
#define SM_A 0              // A tile: 128 * 272 = 34816 B
#define SM_B 34816          // B tile: 128 * 272 = 34816 B
#define SM_TOTAL 69632

__device__ __forceinline__ void mma16816(float* c, const uint32_t* a,
                                         const uint32_t* b) {
    asm volatile(
        "mma.sync.aligned.m16n8k16.row.col.f32.f16.f16.f32 "
        "{%0,%1,%2,%3}, {%4,%5,%6,%7}, {%8,%9}, {%0,%1,%2,%3};"
        : "+f"(c[0]), "+f"(c[1]), "+f"(c[2]), "+f"(c[3])
        : "r"(a[0]), "r"(a[1]), "r"(a[2]), "r"(a[3]), "r"(b[0]), "r"(b[1]));
}

__global__ __launch_bounds__(256, 2)
void node_gemm_mma(const float* __restrict__ embed,
                   const float* __restrict__ W1,
                   const float* __restrict__ b1,
                   const float* __restrict__ W2,
                   const float* __restrict__ b2,
                   const int* __restrict__ srcp,
                   const int* __restrict__ dstp,
                   int M, int nblk) {
    extern __shared__ char smem[];
    int tid = threadIdx.x;

    if (blockIdx.x == (unsigned)nblk) {
        // ---- c vector block: c = emb[src]@W1[256:384] + emb[dst]@W1[384:512] + b1
        __shared__ float part[4][HID];
        int j = tid & 63;
        int g = tid >> 6;   // 0..3
        int s = srcp[0];
        int d = dstp[0];
        const float* es = embed + (size_t)s * D_FEAT;
        const float* ed = embed + (size_t)d * D_FEAT;
        float acc = 0.f;
#pragma unroll 16
        for (int t = g * 64; t < g * 64 + 64; ++t) {
            float e = (t < 128) ? es[t] : ed[t - 128];
            acc = fmaf(e, W1[(256 + t) * HID + j], acc);  // 256+t == 384+(t-128)
        }
        part[g][j] = acc;
        __syncthreads();
        if (tid < 64) {
            float cj = b1[j] + part[0][j] + part[1][j] + part[2][j] + part[3][j];
            g_c[j] = cj;
            part[0][j] = cj;
            if (j == 0) g_c[HID] = b2[0];
        }
        __syncthreads();
        if (tid < 32) {
            g_ch2[tid]  = __floats2half2_rn(part[0][2 * tid], part[0][2 * tid + 1]);
            g_w2h2[tid] = __floats2half2_rn(W2[2 * tid], W2[2 * tid + 1]);
        }
        return;
    }

    int row0 = blockIdx.x * 128;
    int rows = M - row0;
    if (rows > 128) rows = 128;

    // Build WcT smem tile from W1 (coalesced read, transposed half stores).
    for (int idx = tid; idx < 16384; idx += 256) {
        int r = idx >> 6;
        int c = idx & 63;
        int k = (r < 128) ? r : r - 128;
        int j = (r < 128) ? c : c + 64;
        *(__half*)(smem + SM_B + j * SROW + 2 * k) = __float2half_rn(W1[idx]);
    }

    // Load + convert A tile: chunk = 8 floats -> 8 halves (16 B)
    for (int idx = tid; idx < 2048; idx += 256) {
        int r  = idx >> 4;
        int cc = idx & 15;
        float4 f0, f1;
        if (r < rows) {
            const float* src = embed + (size_t)(row0 + r) * 128 + cc * 8;
            f0 = *(const float4*)src;
            f1 = *(const float4*)(src + 4);
        } else {
            f0 = f1 = make_float4(0.f, 0.f, 0.f, 0.f);
        }
        __half2 h[4];
        h[0] = __floats2half2_rn(f0.x, f0.y);
        h[1] = __floats2half2_rn(f0.z, f0.w);
        h[2] = __floats2half2_rn(f1.x, f1.y);
        h[3] = __floats2half2_rn(f1.z, f1.w);
        *(uint4*)(smem + SM_A + r * SROW + cc * 16) = *(uint4*)h;
    }
    __syncthreads();

    int w    = tid >> 5;
    int lane = tid & 31;
    int g    = lane >> 2;
    int tg   = lane & 3;
    int mw   = (w & 3) * 32;
    int nw   = (w >> 2) * 64;

    float acc[2][8][4];
#pragma unroll
    for (int mi = 0; mi < 2; ++mi)
#pragma unroll
        for (int nj = 0; nj < 8; ++nj)
#pragma unroll
            for (int q = 0; q < 4; ++q) acc[mi][nj][q] = 0.f;

    const char* pa0 = smem + SM_A + (mw + g) * SROW + tg * 4;
    const char* pb0 = smem + SM_B + (nw + g) * SROW + tg * 4;

#pragma unroll
    for (int ks = 0; ks < 8; ++ks) {
        int kb = ks * 32;
        uint32_t a[2][4];
#pragma unroll
        for (int mi = 0; mi < 2; ++mi) {
            const char* p = pa0 + mi * 16 * SROW + kb;
            a[mi][0] = *(const uint32_t*)p;
            a[mi][1] = *(const uint32_t*)(p + 8 * SROW);
            a[mi][2] = *(const uint32_t*)(p + 16);
            a[mi][3] = *(const uint32_t*)(p + 8 * SROW + 16);
        }
        uint32_t b[8][2];
#pragma unroll
        for (int nj = 0; nj < 8; ++nj) {
            const char* p = pb0 + nj * 8 * SROW + kb;
            b[nj][0] = *(const uint32_t*)p;
            b[nj][1] = *(const uint32_t*)(p + 16);
        }
#pragma unroll
        for (int mi = 0; mi < 2; ++mi)
#pragma unroll
            for (int nj = 0; nj < 8; ++nj)
                mma16816(acc[mi][nj], a[mi], b[nj]);
    }

#pragma unroll
    for (int mi = 0; mi < 2; ++mi) {
        int r0 = row0 + mw + mi * 16 + g;
        int r1 = r0 + 8;
#pragma unroll
        for (int nj = 0; nj < 8; ++nj) {
            int jc = nw + nj * 8 + tg * 2;
            if (r0 < M)
                *(__half2*)(g_yh + (size_t)r0 * 128 + jc) =
                    __floats2half2_rn(acc[mi][nj][0], acc[mi][nj][1]);
            if (r1 < M)
                *(__half2*)(g_yh + (size_t)r1 * 128 + jc) =
                    __floats2half2_rn(acc[mi][nj][2], acc[mi][nj][3]);
        }
    }
}

// ---------------------------------------------------------------------------
// Kernel 2: edge kernel — 8 edges per warp iteration (2 quads), 8 lanes/edge,
// half2 math. Gate: sigmoid(logit(n)+s) == n*exp(s) / (n*exp(s) + 1 - n).
// ---------------------------------------------------------------------------
__global__ void edge_kernel(const float* __restrict__ noise,
                            const int* __restrict__ col,
                            const int* __restrict__ row,
                            float* __restrict__ out,
                            int E) {
    int lane = threadIdx.x & 31;
    int sub  = lane >> 3;
    int l8   = lane & 7;
    int warp  = blockIdx.x * (blockDim.x >> 5) + (threadIdx.x >> 5);
    int nwarp = gridDim.x * (blockDim.x >> 5);

    uint4 cu = *(const uint4*)&g_ch2[l8 * 4];
    uint4 wu = *(const uint4*)&g_w2h2[l8 * 4];
    const __half2* c2 = (const __half2*)&cu;
    const __half2* w2 = (const __half2*)&wu;
    float bias = g_c[HID];
    __half2 z2 = __float2half2_rn(0.f);

    for (int base = 8 * warp; base < E; base += 8 * nwarp) {
        int e0 = base + sub;
        int e1 = base + 4 + sub;
        bool ok0 = e0 < E, ok1 = e1 < E;
        int i0 = ok0 ? e0 : 0, i1 = ok1 ? e1 : 0;

        int ci0 = col[i0], ri0 = row[i0];
        int ci1 = col[i1], ri1 = row[i1];

        uint4 av0 = __ldg((const uint4*)(g_yh + (size_t)ci0 * 128 + l8 * 8));
        uint4 bv0 = __ldg((const uint4*)(g_yh + (size_t)ri0 * 128 + 64 + l8 * 8));
        uint4 av1 = __ldg((const uint4*)(g_yh + (size_t)ci1 * 128 + l8 * 8));
        uint4 bv1 = __ldg((const uint4*)(g_yh + (size_t)ri1 * 128 + 64 + l8 * 8));

        const __half2* ah0 = (const __half2*)&av0;
        const __half2* bh0 = (const __half2*)&bv0;
        const __half2* ah1 = (const __half2*)&av1;
        const __half2* bh1 = (const __half2*)&bv1;

        __half2 p0 = __hmax2(__hadd2(__hadd2(ah0[0], bh0[0]), c2[0]), z2);
        __half2 p1 = __hmax2(__hadd2(__hadd2(ah0[1], bh0[1]), c2[1]), z2);
        __half2 p2 = __hmax2(__hadd2(__hadd2(ah0[2], bh0[2]), c2[2]), z2);
        __half2 p3 = __hmax2(__hadd2(__hadd2(ah0[3], bh0[3]), c2[3]), z2);
        __half2 q0 = __hmax2(__hadd2(__hadd2(ah1[0], bh1[0]), c2[0]), z2);
        __half2 q1 = __hmax2(__hadd2(__hadd2(ah1[1], bh1[1]), c2[1]), z2);
        __half2 q2 = __hmax2(__hadd2(__hadd2(ah1[2], bh1[2]), c2[2]), z2);
        __half2 q3 = __hmax2(__hadd2(__hadd2(ah1[3], bh1[3]), c2[3]), z2);

        __half2 sa0 = __hfma2(p1, w2[1], __hmul2(p0, w2[0]));
        __half2 sb0 = __hfma2(p3, w2[3], __hmul2(p2, w2[2]));
        __half2 sa1 = __hfma2(q1, w2[1], __hmul2(q0, w2[0]));
        __half2 sb1 = __hfma2(q3, w2[3], __hmul2(q2, w2[2]));

        float2 fa0 = __half22float2(sa0), fb0 = __half22float2(sb0);
        float2 fa1 = __half22float2(sa1), fb1 = __half22float2(sb1);
        float s0 = (fa0.x + fa0.y) + (fb0.x + fb0.y);
        float s1 = (fa1.x + fa1.y) + (fb1.x + fb1.y);

        s0 += __shfl_xor_sync(0xffffffffu, s0, 4);
        s0 += __shfl_xor_sync(0xffffffffu, s0, 2);
        s0 += __shfl_xor_sync(0xffffffffu, s0, 1);
        s1 += __shfl_xor_sync(0xffffffffu, s1, 4);
        s1 += __shfl_xor_sync(0xffffffffu, s1, 2);
        s1 += __shfl_xor_sync(0xffffffffu, s1, 1);

        if (l8 == 0) {
            if (ok0) {
                float n = noise[e0];
                float t = n * expf(s0 + bias);
                out[e0] = t / (t + 1.f - n);
            }
            if (ok1) {
                float n = noise[e1];
                float t = n * expf(s1 + bias);
                out[e1] = t / (t + 1.f - n);
            }
        }
    }
}

// ---------------------------------------------------------------------------
extern "C" void kernel_launch(void* const* d_in, const int* in_sizes, int n_in,
                              void* d_out, int out_size) {
    const float* embed = (const float*)d_in[0];
    const float* W1    = (const float*)d_in[1];
    const float* b1    = (const float*)d_in[2];
    const float* W2    = (const float*)d_in[3];
    const float* b2    = (const float*)d_in[4];
    const float* noise = (const float*)d_in[5];
    const int*   col   = (const int*)d_in[6];
    const int*   row   = (const int*)d_in[7];
    const int*   srcp  = (const int*)d_in[8];
    const int*   dstp  = (const int*)d_in[9];

    int M = in_sizes[0] / D_FEAT;
    int E = in_sizes[6];

    cudaFuncSetAttribute(node_gemm_mma,
                         cudaFuncAttributeMaxDynamicSharedMemorySize, SM_TOTAL);

    int nblk = (M + 127) / 128;
    node_gemm_mma<<<nblk + 1, 256, SM_TOTAL>>>(embed, W1, b1, W2, b2,
                                               srcp, dstp, M, nblk);
    edge_kernel<<<4096, 256>>>(noise, col, row, (float*)d_out, E);
}